// round 9
// baseline (speedup 1.0000x reference)
#include <cuda_runtime.h>
#include <math.h>

#define BATCH 16
#define IMH 28
#define IMW 28
#define KS 5
#define OH 24
#define OW 24
#define NP 576          // OH*OW patches per batch
#define KNUM 16

// ---------------------------------------------------------------------------
// R4 structure (best measured): grid (72,16), 256 threads, 8 warps, warp owns
// one p-row; per-chunk compute -> smem stage -> 512B-contiguous store rounds.
// Single change vs R8: __launch_bounds__(256, 5) -> 5 resident blocks/SM
// (regs capped at 51; R3/R7 compiled this body at 48-51, no spill expected).
// Blocks x<3 also compute the mu conv outputs for their batch.
// ---------------------------------------------------------------------------
__global__ void __launch_bounds__(256, 5) fused_kernel(
        const float* __restrict__ in,       // [16,28,28,1]
        const float* __restrict__ w_mu,     // [5,5,1,16]
        const float* __restrict__ w_sigma,  // [16]
        float* __restrict__ out)            // mu_out ++ Sigma
{
    __shared__ __align__(16) float simg[IMH * IMW];   // 784 floats
    __shared__ float sscale[KNUM];
    __shared__ float sw[KS * KS * KNUM];              // mu blocks only
    __shared__ __align__(16) float sG[8 * 128];       // per-warp G staging

    const int b   = blockIdx.y;
    const int tid = threadIdx.x;

    const float* img = in + (size_t)b * IMH * IMW;
    for (int i = tid; i < IMH * IMW; i += 256) simg[i] = img[i];
    if (tid < KNUM) sscale[tid] = log1pf(expf(w_sigma[tid]));
    if (blockIdx.x < 3)
        for (int i = tid; i < KS * KS * KNUM; i += 256) sw[i] = w_mu[i];
    __syncthreads();

    // ---- mu path (3 blocks x 256 threads cover 576 outputs per batch) ----
    if (blockIdx.x < 3) {
        int pos = blockIdx.x * 256 + tid;
        if (pos < NP) {
            int y = pos / OW;
            int x = pos - y * OW;
            float acc[KNUM];
#pragma unroll
            for (int k = 0; k < KNUM; k++) acc[k] = 0.f;
#pragma unroll
            for (int i = 0; i < KS; i++)
#pragma unroll
                for (int j = 0; j < KS; j++) {
                    float v = simg[(y + i) * IMW + (x + j)];
                    const float* wk = &sw[(i * KS + j) * KNUM];
#pragma unroll
                    for (int k = 0; k < KNUM; k++) acc[k] = fmaf(v, wk[k], acc[k]);
                }
            float4* o = reinterpret_cast<float4*>(
                out + ((size_t)b * NP + pos) * KNUM);
            o[0] = make_float4(acc[0],  acc[1],  acc[2],  acc[3]);
            o[1] = make_float4(acc[4],  acc[5],  acc[6],  acc[7]);
            o[2] = make_float4(acc[8],  acc[9],  acc[10], acc[11]);
            o[3] = make_float4(acc[12], acc[13], acc[14], acc[15]);
        }
    }

    // ---- Sigma path ----
    const int warp = tid >> 5;
    const int lane = tid & 31;
    const int p    = blockIdx.x * 8 + warp;
    const int pr   = p / OW;
    const int pc   = p - pr * OW;

    // patch_p in registers (uniform smem addr across warp -> broadcast LDS)
    float a[KS * KS];
#pragma unroll
    for (int i = 0; i < KS; i++)
#pragma unroll
        for (int j = 0; j < KS; j++)
            a[i * KS + j] = simg[(pr + i) * IMW + pc + j];

    const int sub = lane >> 2;          // 0..7  q sub-index in a store round
    const int kg  = (lane & 3) << 2;    // 0,4,8,12 k-group base
    const float sc0 = sscale[kg + 0];
    const float sc1 = sscale[kg + 1];
    const float sc2 = sscale[kg + 2];
    const float sc3 = sscale[kg + 3];

    float* sigma = out + (size_t)BATCH * NP * KNUM;
    const size_t rowbase = ((size_t)b * NP + p) * NP;
    float* gslot = &sG[warp * 128 + lane * 4];

    for (int qb = 0; qb < NP; qb += 128) {
        // ---- compute: 4 consecutive q per lane ----
        int q0 = qb + 4 * lane;
        if (q0 >= NP) q0 = 0;           // tail lanes compute dummy (not stored)
        const int qr  = q0 / OW;
        const int qc0 = q0 - qr * OW;   // multiple of 4

        float acc0 = 0.f, acc1 = 0.f, acc2 = 0.f, acc3 = 0.f;
#pragma unroll
        for (int i = 0; i < KS; i++) {
            const float4* rowp = reinterpret_cast<const float4*>(
                simg + (qr + i) * IMW + qc0);
            float4 v0 = rowp[0];
            float4 v1 = rowp[1];
            float r8[8] = {v0.x, v0.y, v0.z, v0.w, v1.x, v1.y, v1.z, v1.w};
#pragma unroll
            for (int k = 0; k < KS; k++) {
                float w = a[i * KS + k];
                acc0 = fmaf(w, r8[k + 0], acc0);
                acc1 = fmaf(w, r8[k + 1], acc1);
                acc2 = fmaf(w, r8[k + 2], acc2);
                acc3 = fmaf(w, r8[k + 3], acc3);
            }
        }
        if (!isfinite(acc0)) acc0 = 0.f;
        if (!isfinite(acc1)) acc1 = 0.f;
        if (!isfinite(acc2)) acc2 = 0.f;
        if (!isfinite(acc3)) acc3 = 0.f;

        // ---- stage G through smem (STS.128, conflict-free) ----
        __syncwarp();
        *reinterpret_cast<float4*>(gslot) = make_float4(acc0, acc1, acc2, acc3);
        __syncwarp();

        // ---- store rounds: 512B-contiguous STG.128 per round ----
        float4* obase = reinterpret_cast<float4*>(sigma + (rowbase + qb) * KNUM);
        const int nr = (NP - qb >= 128) ? 16 : (NP - qb) / 8;

        if (qb != 0) {
#pragma unroll 4
            for (int r = 0; r < nr; r++) {
                float g = sG[warp * 128 + r * 8 + sub];   // broadcast LDS
                float4 v = make_float4(sc0 * g, sc1 * g, sc2 * g, sc3 * g);
                obase[r * 32 + lane] = v;
            }
        } else {
            // first chunk: diag abs for q < 16 (rounds 0,1)
#pragma unroll
            for (int r = 0; r < 16; r++) {
                int qq = r * 8 + sub;
                float g = sG[warp * 128 + qq];
                float4 v = make_float4(sc0 * g, sc1 * g, sc2 * g, sc3 * g);
                if (r < 2) {
                    if (qq == kg + 0) v.x = fabsf(v.x);
                    if (qq == kg + 1) v.y = fabsf(v.y);
                    if (qq == kg + 2) v.z = fabsf(v.z);
                    if (qq == kg + 3) v.w = fabsf(v.w);
                }
                obase[r * 32 + lane] = v;
            }
        }
    }
}

// ---------------------------------------------------------------------------
// Inputs (metadata order): mu_in [16,28,28,1] f32, w_mu [5,5,1,16] f32,
// w_sigma [16] f32. Output: mu_out (147456 f32) ++ Sigma (84934656 f32).
// ---------------------------------------------------------------------------
extern "C" void kernel_launch(void* const* d_in, const int* in_sizes, int n_in,
                              void* d_out, int out_size)
{
    const float* mu_in   = (const float*)d_in[0];
    const float* w_mu    = (const float*)d_in[1];
    const float* w_sigma = (const float*)d_in[2];
    float* out = (float*)d_out;

    fused_kernel<<<dim3(NP / 8, BATCH), 256>>>(mu_in, w_mu, w_sigma, out);
}

// round 10
// speedup vs baseline: 1.0708x; 1.0708x over previous
#include <cuda_runtime.h>
#include <math.h>

#define BATCH 16
#define IMH 28
#define IMW 28
#define KS 5
#define OH 24
#define OW 24
#define NP 576          // OH*OW patches per batch
#define KNUM 16

// ---------------------------------------------------------------------------
// R8 structure (best measured): grid (72,16), 256 threads, 8 warps, warp owns
// one p-row; per-chunk compute -> smem stage -> 512B-contiguous store rounds;
// default write-back stores; natural reg allocation (4 blocks/SM).
// Single change vs R8: mu conv spread uniformly — every block computes 8 mu
// outputs (lanes 0-7 of warp 0) instead of 48 straggler blocks doing 256 each.
// ---------------------------------------------------------------------------
__global__ void __launch_bounds__(256) fused_kernel(
        const float* __restrict__ in,       // [16,28,28,1]
        const float* __restrict__ w_mu,     // [5,5,1,16]
        const float* __restrict__ w_sigma,  // [16]
        float* __restrict__ out)            // mu_out ++ Sigma
{
    __shared__ __align__(16) float simg[IMH * IMW];   // 784 floats
    __shared__ float sscale[KNUM];
    __shared__ float sw[KS * KS * KNUM];              // 400 floats
    __shared__ __align__(16) float sG[8 * 128];       // per-warp G staging

    const int b   = blockIdx.y;
    const int tid = threadIdx.x;

    const float* img = in + (size_t)b * IMH * IMW;
    for (int i = tid; i < IMH * IMW; i += 256) simg[i] = img[i];
    if (tid < KNUM) sscale[tid] = log1pf(expf(w_sigma[tid]));
    for (int i = tid; i < KS * KS * KNUM; i += 256) sw[i] = w_mu[i];
    __syncthreads();

    // ---- mu path: 8 outputs per block (lanes 0-7 of warp 0), 72*8 = 576 ----
    if (tid < 8) {
        int pos = blockIdx.x * 8 + tid;
        int y = pos / OW;
        int x = pos - y * OW;
        float acc[KNUM];
#pragma unroll
        for (int k = 0; k < KNUM; k++) acc[k] = 0.f;
#pragma unroll
        for (int i = 0; i < KS; i++)
#pragma unroll
            for (int j = 0; j < KS; j++) {
                float v = simg[(y + i) * IMW + (x + j)];
                const float* wk = &sw[(i * KS + j) * KNUM];
#pragma unroll
                for (int k = 0; k < KNUM; k++) acc[k] = fmaf(v, wk[k], acc[k]);
            }
        float4* o = reinterpret_cast<float4*>(
            out + ((size_t)b * NP + pos) * KNUM);
        o[0] = make_float4(acc[0],  acc[1],  acc[2],  acc[3]);
        o[1] = make_float4(acc[4],  acc[5],  acc[6],  acc[7]);
        o[2] = make_float4(acc[8],  acc[9],  acc[10], acc[11]);
        o[3] = make_float4(acc[12], acc[13], acc[14], acc[15]);
    }

    // ---- Sigma path ----
    const int warp = tid >> 5;
    const int lane = tid & 31;
    const int p    = blockIdx.x * 8 + warp;
    const int pr   = p / OW;
    const int pc   = p - pr * OW;

    // patch_p in registers (uniform smem addr across warp -> broadcast LDS)
    float a[KS * KS];
#pragma unroll
    for (int i = 0; i < KS; i++)
#pragma unroll
        for (int j = 0; j < KS; j++)
            a[i * KS + j] = simg[(pr + i) * IMW + pc + j];

    const int sub = lane >> 2;          // 0..7  q sub-index in a store round
    const int kg  = (lane & 3) << 2;    // 0,4,8,12 k-group base
    const float sc0 = sscale[kg + 0];
    const float sc1 = sscale[kg + 1];
    const float sc2 = sscale[kg + 2];
    const float sc3 = sscale[kg + 3];

    float* sigma = out + (size_t)BATCH * NP * KNUM;
    const size_t rowbase = ((size_t)b * NP + p) * NP;
    float* gslot = &sG[warp * 128 + lane * 4];

    for (int qb = 0; qb < NP; qb += 128) {
        // ---- compute: 4 consecutive q per lane ----
        int q0 = qb + 4 * lane;
        if (q0 >= NP) q0 = 0;           // tail lanes compute dummy (not stored)
        const int qr  = q0 / OW;
        const int qc0 = q0 - qr * OW;   // multiple of 4

        float acc0 = 0.f, acc1 = 0.f, acc2 = 0.f, acc3 = 0.f;
#pragma unroll
        for (int i = 0; i < KS; i++) {
            const float4* rowp = reinterpret_cast<const float4*>(
                simg + (qr + i) * IMW + qc0);
            float4 v0 = rowp[0];
            float4 v1 = rowp[1];
            float r8[8] = {v0.x, v0.y, v0.z, v0.w, v1.x, v1.y, v1.z, v1.w};
#pragma unroll
            for (int k = 0; k < KS; k++) {
                float w = a[i * KS + k];
                acc0 = fmaf(w, r8[k + 0], acc0);
                acc1 = fmaf(w, r8[k + 1], acc1);
                acc2 = fmaf(w, r8[k + 2], acc2);
                acc3 = fmaf(w, r8[k + 3], acc3);
            }
        }
        if (!isfinite(acc0)) acc0 = 0.f;
        if (!isfinite(acc1)) acc1 = 0.f;
        if (!isfinite(acc2)) acc2 = 0.f;
        if (!isfinite(acc3)) acc3 = 0.f;

        // ---- stage G through smem (STS.128, conflict-free) ----
        __syncwarp();
        *reinterpret_cast<float4*>(gslot) = make_float4(acc0, acc1, acc2, acc3);
        __syncwarp();

        // ---- store rounds: 512B-contiguous STG.128 per round ----
        float4* obase = reinterpret_cast<float4*>(sigma + (rowbase + qb) * KNUM);
        const int nr = (NP - qb >= 128) ? 16 : (NP - qb) / 8;

        if (qb != 0) {
#pragma unroll 4
            for (int r = 0; r < nr; r++) {
                float g = sG[warp * 128 + r * 8 + sub];   // broadcast LDS
                float4 v = make_float4(sc0 * g, sc1 * g, sc2 * g, sc3 * g);
                obase[r * 32 + lane] = v;
            }
        } else {
            // first chunk: diag abs for q < 16 (rounds 0,1)
#pragma unroll
            for (int r = 0; r < 16; r++) {
                int qq = r * 8 + sub;
                float g = sG[warp * 128 + qq];
                float4 v = make_float4(sc0 * g, sc1 * g, sc2 * g, sc3 * g);
                if (r < 2) {
                    if (qq == kg + 0) v.x = fabsf(v.x);
                    if (qq == kg + 1) v.y = fabsf(v.y);
                    if (qq == kg + 2) v.z = fabsf(v.z);
                    if (qq == kg + 3) v.w = fabsf(v.w);
                }
                obase[r * 32 + lane] = v;
            }
        }
    }
}

// ---------------------------------------------------------------------------
// Inputs (metadata order): mu_in [16,28,28,1] f32, w_mu [5,5,1,16] f32,
// w_sigma [16] f32. Output: mu_out (147456 f32) ++ Sigma (84934656 f32).
// ---------------------------------------------------------------------------
extern "C" void kernel_launch(void* const* d_in, const int* in_sizes, int n_in,
                              void* d_out, int out_size)
{
    const float* mu_in   = (const float*)d_in[0];
    const float* w_mu    = (const float*)d_in[1];
    const float* w_sigma = (const float*)d_in[2];
    float* out = (float*)d_out;

    fused_kernel<<<dim3(NP / 8, BATCH), 256>>>(mu_in, w_mu, w_sigma, out);
}